// round 15
// baseline (speedup 1.0000x reference)
#include <cuda_runtime.h>
#include <cuda_bf16.h>
#include <cstdint>

#define EPS 1e-5f
typedef unsigned long long u64;
typedef unsigned int u32;
typedef unsigned short u16;

// ---------------- device scratch ----------------
__device__ float g_a2[64], g_b2[64];
__device__ float g_a3[2048], g_b3[2048];
__device__ u64 g_w2bits[64 * 9];
__device__ u64 g_fc1bits[2048 * 49];
__device__ u64 g_fc2bits[10 * 32];
__device__ u64 g_bits1[2048 * 14 * 14];
__device__ u64 g_bits2[2048 * 7 * 7];
__device__ u64 g_bits3[2048 * 32];

// ---------------- packed f32x2 helpers ----------------
__device__ __forceinline__ u64 fma2(u64 a, u64 b, u64 c) {
    u64 d;
    asm("fma.rn.f32x2 %0, %1, %2, %3;" : "=l"(d) : "l"(a), "l"(b), "l"(c));
    return d;
}
__device__ __forceinline__ u64 pack2(float lo, float hi) {
    u64 d;
    asm("mov.b64 %0, {%1, %2};" : "=l"(d) : "f"(lo), "f"(hi));
    return d;
}
__device__ __forceinline__ void unpack2(u64 v, float& lo, float& hi) {
    asm("mov.b64 {%0, %1}, %2;" : "=f"(lo), "=f"(hi) : "l"(v));
}

// ================= kA: conv1 (2-way channel split) + ALL weight prep =================
// conv1: warp-uniform cg = gw&1; thread computes 32 channels of one pooled pixel,
// writes its u32 half of the u64 channel word (little-endian aliasing, no atomics).
#define NB_CONV1 3136               /* 2048*196 px * 2 cg / 256 thr */
#define NB_FC1W  2048
#define NB_W2    64
#define NB_FC2W  10
#define NB_BN    8
#define NB_KA (NB_CONV1 + NB_FC1W + NB_W2 + NB_FC2W + NB_BN)

__global__ __launch_bounds__(256, 5) void kA(
    const float* __restrict__ x, const float* __restrict__ w1,
    const float* __restrict__ g1, const float* __restrict__ be1,
    const float* __restrict__ m1, const float* __restrict__ v1,
    const float* __restrict__ w2,
    const float* __restrict__ wfc1,
    const float* __restrict__ g2, const float* __restrict__ be2,
    const float* __restrict__ m2, const float* __restrict__ v2,
    const float* __restrict__ g3, const float* __restrict__ be3,
    const float* __restrict__ m3, const float* __restrict__ v3,
    const float* __restrict__ wfc2)
{
    __shared__ u64 sw[576];
    __shared__ float sa[64], sb[64];
    __shared__ u32 sbits[98];
    __shared__ u32 sp[98];

    int bid = blockIdx.x;
    int tid = threadIdx.x;

    if (bid < NB_CONV1) {
        // ---- conv1 role: 2 channel-groups, warp-uniform ----
        for (int i = tid; i < 576; i += 256) {
            float s = (w1[i] >= 0.0f) ? 1.0f : -1.0f;
            sw[i] = pack2(s, s);
        }
        if (tid < 64) {
            float a = g1[tid] / sqrtf(v1[tid] + EPS);
            sa[tid] = a;
            sb[tid] = be1[tid] - m1[tid] * a;
        }
        __syncthreads();

        int gw = (bid * 256 + tid) >> 5;   // global warp [0, 25088)
        int lane = tid & 31;
        int cg = gw & 1;                    // uniform within warp
        int pq = (gw >> 1) * 32 + lane;     // pooled pixel [0, 401408)
        int b = pq / 196, p = pq % 196;
        int py = p / 14, px = p % 14;
        const float* xb = x + b * 784;

        u64 pr[4][3];
#pragma unroll
        for (int r = 0; r < 4; r++) {
            int rr = 2 * py - 1 + r; rr = min(max(rr, 0), 27);
            const float* xr = xb + rr * 28;
            int c0 = max(2 * px - 1, 0);
            int c3 = min(2 * px + 2, 27);
            float f0 = xr[c0];
            float f1 = xr[2 * px];
            float f2 = xr[2 * px + 1];
            float f3 = xr[c3];
            pr[r][0] = pack2(f0, f1);
            pr[r][1] = pack2(f1, f2);
            pr[r][2] = pack2(f2, f3);
        }

        u32 word = 0;
        int cobase = cg * 32;
        for (int t = 0; t < 32; t += 2) {
            int co = cobase + t;
            u64 a00 = 0ULL, a01 = 0ULL, a10 = 0ULL, a11 = 0ULL;
            const u64* w0 = &sw[co * 9];
#pragma unroll
            for (int ky = 0; ky < 3; ky++)
#pragma unroll
                for (int kx = 0; kx < 3; kx++) {
                    u64 wa = w0[ky * 3 + kx], wb = w0[9 + ky * 3 + kx];
                    a00 = fma2(wa, pr[ky][kx], a00);
                    a01 = fma2(wa, pr[ky + 1][kx], a01);
                    a10 = fma2(wb, pr[ky][kx], a10);
                    a11 = fma2(wb, pr[ky + 1][kx], a11);
                }
            float v0, v1x, v2, v3;
            unpack2(a00, v0, v1x); unpack2(a01, v2, v3);
            float m0 = fmaxf(fmaxf(v0, v1x), fmaxf(v2, v3));
            unpack2(a10, v0, v1x); unpack2(a11, v2, v3);
            float m1v = fmaxf(fmaxf(v0, v1x), fmaxf(v2, v3));
            if (fmaf(sa[co], m0, sb[co]) >= 0.0f)          word |= 1u << t;
            if (fmaf(sa[co + 1], m1v, sb[co + 1]) >= 0.0f) word |= 1u << (t + 1);
        }
        ((u32*)g_bits1)[(b * 196 + p) * 2 + cg] = word;

    } else if (bid < NB_CONV1 + NB_FC1W) {
        // ---- fc1 weight pack role ----
        int o = bid - NB_CONV1;
        const float* wo = wfc1 + (long long)o * 3136;
#pragma unroll
        for (int it = 0; it < 13; it++) {
            int i = it * 256 + tid;
            bool v = (i < 3136) ? (wo[i] >= 0.0f) : false;
            u32 m = __ballot_sync(0xffffffffu, v);
            if ((tid & 31) == 0 && i < 3136) sbits[i >> 5] = m;
        }
        __syncthreads();
        if (tid < 98) {
            int j = tid % 49, half = tid / 49;
            u32 part = 0;
#pragma unroll
            for (int cc = 0; cc < 32; cc++) {
                int c = half * 32 + cc;
                int fi = c * 49 + j;
                part |= ((sbits[fi >> 5] >> (fi & 31)) & 1u) << cc;
            }
            sp[tid] = part;
        }
        __syncthreads();
        if (tid < 49)
            g_fc1bits[o * 49 + tid] = (u64)sp[tid] | ((u64)sp[tid + 49] << 32);

    } else if (bid < NB_CONV1 + NB_FC1W + NB_W2) {
        // ---- conv2 weight pack role ----
        int co = bid - NB_CONV1 - NB_FC1W;
        const float* wc = w2 + co * 576;
#pragma unroll
        for (int it = 0; it < 3; it++) {
            int i = it * 256 + tid;
            bool v = (i < 576) ? (wc[i] >= 0.0f) : false;
            u32 m = __ballot_sync(0xffffffffu, v);
            if ((tid & 31) == 0 && i < 576) sbits[i >> 5] = m;
        }
        __syncthreads();
        if (tid < 9) {
            u64 word = 0ULL;
#pragma unroll
            for (int cin = 0; cin < 64; cin++) {
                int fi = cin * 9 + tid;
                word |= (u64)((sbits[fi >> 5] >> (fi & 31)) & 1u) << cin;
            }
            g_w2bits[co * 9 + tid] = word;
        }

    } else if (bid < NB_CONV1 + NB_FC1W + NB_W2 + NB_FC2W) {
        // ---- fc2 weight pack role ----
        int o = bid - NB_CONV1 - NB_FC1W - NB_W2;
        const float* wo = wfc2 + o * 2048;
#pragma unroll
        for (int it = 0; it < 8; it++) {
            int i = it * 256 + tid;
            u32 m = __ballot_sync(0xffffffffu, wo[i] >= 0.0f);
            if ((tid & 31) == 0) sbits[i >> 5] = m;
        }
        __syncthreads();
        if (tid < 32)
            g_fc2bits[o * 32 + tid] = (u64)sbits[2 * tid] | ((u64)sbits[2 * tid + 1] << 32);

    } else {
        // ---- bn fold role ----
        int i = (bid - NB_CONV1 - NB_FC1W - NB_W2 - NB_FC2W) * 256 + tid;
        if (i < 2048) {
            float a = g3[i] / sqrtf(v3[i] + EPS);
            g_a3[i] = a;
            g_b3[i] = be3[i] - m3[i] * a;
        }
        if (i < 64) {
            float a = g2[i] / sqrtf(v2[i] + EPS);
            g_a2[i] = a;
            g_b2[i] = be2[i] - m2[i] * a;
        }
    }
}

// ================= conv2: window-split across lanes (r14 + occupancy cap) =================
__global__ __launch_bounds__(256, 6) void conv2_kernel(int base) {
    __shared__ __align__(16) u64 sw[640];   // stride 10 per co
    __shared__ float sa[64], sb[64];
    int tid = threadIdx.x;
    for (int i = tid; i < 576; i += 256) {
        int co = i / 9, q = i - co * 9;
        sw[co * 10 + q] = g_w2bits[i];
    }
    if (tid < 64) { sa[tid] = g_a2[tid]; sb[tid] = g_b2[tid]; }
    __syncthreads();

    int gw = ((base + blockIdx.x) * 256 + tid) >> 5;  // global warp [0, 50176)
    int lane = tid & 31;
    int cg = gw & 3;                          // uniform within warp
    int oct = gw >> 2;                        // pooled-pixel octet [0, 12544)
    int o8 = lane >> 2;
    int spv = lane & 3;
    int pp = oct * 8 + o8;                    // [0, 2048*49)
    int b = pp / 49, p = pp % 49;
    int py = p / 7, px = p % 7;
    int dy = spv >> 1, dx = spv & 1;
    const u64* ib = g_bits1 + b * 196;

    u64 pix[9];
#pragma unroll
    for (int ky = 0; ky < 3; ky++) {
        int r = 2 * py - 1 + dy + ky; r = min(max(r, 0), 13);
#pragma unroll
        for (int kx = 0; kx < 3; kx++) {
            int c = 2 * px - 1 + dx + kx; c = min(max(c, 0), 13);
            pix[ky * 3 + kx] = ib[r * 14 + c];
        }
    }

    u32 bits16 = 0;
    int co0 = cg * 16;
#pragma unroll 4
    for (int t = 0; t < 16; t++) {
        const u64* wp = &sw[(co0 + t) * 10];
        int s = 0;
#pragma unroll
        for (int q = 0; q < 9; q++)
            s += __popcll(pix[q] ^ wp[q]);
        s = min(s, __shfl_xor_sync(0xffffffffu, s, 1));
        s = min(s, __shfl_xor_sync(0xffffffffu, s, 2));
        float d = (float)(576 - 2 * s);
        if (fmaf(sa[co0 + t], d, sb[co0 + t]) >= 0.0f) bits16 |= 1u << t;
    }
    if (spv == 0)
        ((u16*)g_bits2)[pp * 4 + cg] = (u16)bits16;
}

// ================= fc1: 64x64 XNOR GEMM + bn3 + sign + pack (known-good) =================
__global__ __launch_bounds__(256) void fc1_kernel() {
    __shared__ u64 sA[64][25];
    __shared__ u64 sB[64][25];
    __shared__ u64 obits[64];
    __shared__ float sa3[64], sb3[64];
    int tid = threadIdx.x;
    int tx = tid & 15, ty = tid >> 4;
    int m0 = blockIdx.y * 64;
    int n0 = blockIdx.x * 64;

    if (tid < 64) {
        obits[tid] = 0ULL;
        sa3[tid] = g_a3[n0 + tid];
        sb3[tid] = g_b3[n0 + tid];
    }

    int acc[4][4];
#pragma unroll
    for (int i = 0; i < 4; i++)
#pragma unroll
        for (int j = 0; j < 4; j++) acc[i][j] = 0;

    for (int e = tid; e < 64 * 25; e += 256) {
        int r = e / 25, kk = e % 25;
        sA[r][kk] = g_bits2[(m0 + r) * 49 + kk];
        sB[r][kk] = g_fc1bits[(n0 + r) * 49 + kk];
    }
    __syncthreads();
#pragma unroll 5
    for (int kk = 0; kk < 25; kk++) {
        u64 a0 = sA[ty][kk], a1 = sA[ty + 16][kk], a2 = sA[ty + 32][kk], a3 = sA[ty + 48][kk];
        u64 b0 = sB[tx][kk], b1 = sB[tx + 16][kk], b2 = sB[tx + 32][kk], b3 = sB[tx + 48][kk];
        acc[0][0] += __popcll(a0 ^ b0); acc[0][1] += __popcll(a0 ^ b1);
        acc[0][2] += __popcll(a0 ^ b2); acc[0][3] += __popcll(a0 ^ b3);
        acc[1][0] += __popcll(a1 ^ b0); acc[1][1] += __popcll(a1 ^ b1);
        acc[1][2] += __popcll(a1 ^ b2); acc[1][3] += __popcll(a1 ^ b3);
        acc[2][0] += __popcll(a2 ^ b0); acc[2][1] += __popcll(a2 ^ b1);
        acc[2][2] += __popcll(a2 ^ b2); acc[2][3] += __popcll(a2 ^ b3);
        acc[3][0] += __popcll(a3 ^ b0); acc[3][1] += __popcll(a3 ^ b1);
        acc[3][2] += __popcll(a3 ^ b2); acc[3][3] += __popcll(a3 ^ b3);
    }
    __syncthreads();
    for (int e = tid; e < 64 * 24; e += 256) {
        int r = e / 24, kk = e % 24;
        sA[r][kk] = g_bits2[(m0 + r) * 49 + 25 + kk];
        sB[r][kk] = g_fc1bits[(n0 + r) * 49 + 25 + kk];
    }
    __syncthreads();
#pragma unroll 4
    for (int kk = 0; kk < 24; kk++) {
        u64 a0 = sA[ty][kk], a1 = sA[ty + 16][kk], a2 = sA[ty + 32][kk], a3 = sA[ty + 48][kk];
        u64 b0 = sB[tx][kk], b1 = sB[tx + 16][kk], b2 = sB[tx + 32][kk], b3 = sB[tx + 48][kk];
        acc[0][0] += __popcll(a0 ^ b0); acc[0][1] += __popcll(a0 ^ b1);
        acc[0][2] += __popcll(a0 ^ b2); acc[0][3] += __popcll(a0 ^ b3);
        acc[1][0] += __popcll(a1 ^ b0); acc[1][1] += __popcll(a1 ^ b1);
        acc[1][2] += __popcll(a1 ^ b2); acc[1][3] += __popcll(a1 ^ b3);
        acc[2][0] += __popcll(a2 ^ b0); acc[2][1] += __popcll(a2 ^ b1);
        acc[2][2] += __popcll(a2 ^ b2); acc[2][3] += __popcll(a2 ^ b3);
        acc[3][0] += __popcll(a3 ^ b0); acc[3][1] += __popcll(a3 ^ b1);
        acc[3][2] += __popcll(a3 ^ b2); acc[3][3] += __popcll(a3 ^ b3);
    }

#pragma unroll
    for (int i = 0; i < 4; i++) {
        u64 bits = 0ULL;
#pragma unroll
        for (int j = 0; j < 4; j++) {
            int c = tx + 16 * j;
            float d = (float)(3136 - 2 * acc[i][j]);
            if (fmaf(sa3[c], d, sb3[c]) >= 0.0f) bits |= 1ULL << c;
        }
        atomicOr(&obits[ty + 16 * i], bits);
    }
    __syncthreads();
    if (tid < 64)
        g_bits3[(m0 + tid) * 32 + blockIdx.x] = obits[tid];
}

// ================= fc2: warp-per-row XNOR + scale (known-good) =================
__global__ __launch_bounds__(256) void fc2_kernel(float* __restrict__ out,
                                                  const float* __restrict__ scale) {
    __shared__ u64 sw[10][32];
    int tid = threadIdx.x;
    for (int i = tid; i < 320; i += 256)
        ((u64*)sw)[i] = g_fc2bits[i];
    __syncthreads();

    int warp = tid >> 5, lane = tid & 31;
    int b = blockIdx.x * 8 + warp;
    u64 xw = g_bits3[b * 32 + lane];
    float sc = scale[0];
#pragma unroll
    for (int o = 0; o < 10; o++) {
        u32 p = (u32)__popcll(xw ^ sw[o][lane]);
        u32 s = __reduce_add_sync(0xffffffffu, p);
        if (lane == o)
            out[b * 10 + o] = sc * (float)(2048 - 2 * (int)s);
    }
}

// ================= launch =================
extern "C" void kernel_launch(void* const* d_in, const int* in_sizes, int n_in,
                              void* d_out, int out_size) {
    const float* x       = (const float*)d_in[0];
    const float* conv1_w = (const float*)d_in[1];
    const float* bn1_g   = (const float*)d_in[2];
    const float* bn1_b   = (const float*)d_in[3];
    const float* bn1_m   = (const float*)d_in[4];
    const float* bn1_v   = (const float*)d_in[5];
    const float* conv2_w = (const float*)d_in[6];
    const float* bn2_g   = (const float*)d_in[7];
    const float* bn2_b   = (const float*)d_in[8];
    const float* bn2_m   = (const float*)d_in[9];
    const float* bn2_v   = (const float*)d_in[10];
    const float* fc1_w   = (const float*)d_in[11];
    const float* bn3_g   = (const float*)d_in[12];
    const float* bn3_b   = (const float*)d_in[13];
    const float* bn3_m   = (const float*)d_in[14];
    const float* bn3_v   = (const float*)d_in[15];
    const float* fc2_w   = (const float*)d_in[16];
    const float* scale   = (const float*)d_in[17];
    float* out = (float*)d_out;

    // launch order: fc1 is #4 (observed ncu capture slot)
    kA<<<NB_KA, 256>>>(x, conv1_w, bn1_g, bn1_b, bn1_m, bn1_v,
                       conv2_w, fc1_w,
                       bn2_g, bn2_b, bn2_m, bn2_v,
                       bn3_g, bn3_b, bn3_m, bn3_v, fc2_w);
    conv2_kernel<<<3136, 256>>>(0);
    conv2_kernel<<<3136, 256>>>(3136);
    fc1_kernel<<<dim3(32, 32), 256>>>();
    fc2_kernel<<<256, 256>>>(out, scale);
}

// round 16
// speedup vs baseline: 1.1523x; 1.1523x over previous
#include <cuda_runtime.h>
#include <cuda_bf16.h>
#include <cstdint>

#define EPS 1e-5f
typedef unsigned long long u64;
typedef unsigned int u32;
typedef unsigned short u16;

// ---------------- device scratch ----------------
__device__ float g_a2[64], g_b2[64];
__device__ float g_a3[2048], g_b3[2048];
__device__ u64 g_w2bits[64 * 9];
__device__ u64 g_fc1bits[2048 * 49];
__device__ u64 g_fc2bits[10 * 32];
__device__ u64 g_bits1[2048 * 14 * 14];
__device__ u64 g_bits2[2048 * 7 * 7];
__device__ u64 g_bits3[2048 * 32];

// ---------------- packed f32x2 helpers ----------------
__device__ __forceinline__ u64 fma2(u64 a, u64 b, u64 c) {
    u64 d;
    asm("fma.rn.f32x2 %0, %1, %2, %3;" : "=l"(d) : "l"(a), "l"(b), "l"(c));
    return d;
}
__device__ __forceinline__ u64 pack2(float lo, float hi) {
    u64 d;
    asm("mov.b64 %0, {%1, %2};" : "=l"(d) : "f"(lo), "f"(hi));
    return d;
}
__device__ __forceinline__ void unpack2(u64 v, float& lo, float& hi) {
    asm("mov.b64 {%0, %1}, %2;" : "=f"(lo), "=f"(hi) : "l"(v));
}
// CSA full adder: sum = a^b^c (1 LOP3/word-half), carry = maj(a,b,c) (1 LOP3/word-half)
__device__ __forceinline__ u64 xor3(u64 a, u64 b, u64 c) { return a ^ b ^ c; }
__device__ __forceinline__ u64 maj3(u64 a, u64 b, u64 c) { return (a & b) | (c & (a ^ b)); }

// ================= kA: conv1 full + heavy weight prep (r14 known-good) =================
#define NB_CONV1 1568
#define NB_FC1W  2048
#define NB_W2    64
#define NB_KA (NB_CONV1 + NB_FC1W + NB_W2)

__global__ __launch_bounds__(256, 4) void kA(
    const float* __restrict__ x, const float* __restrict__ w1,
    const float* __restrict__ g1, const float* __restrict__ be1,
    const float* __restrict__ m1, const float* __restrict__ v1,
    const float* __restrict__ w2,
    const float* __restrict__ wfc1)
{
    __shared__ u64 sw[576];
    __shared__ float sa[64], sb[64];
    __shared__ u32 sbits[98];
    __shared__ u32 sp[98];

    int bid = blockIdx.x;
    int tid = threadIdx.x;

    if (bid < NB_CONV1) {
        // ---- conv1 role ----
        for (int i = tid; i < 576; i += 256) {
            float s = (w1[i] >= 0.0f) ? 1.0f : -1.0f;
            sw[i] = pack2(s, s);
        }
        if (tid < 64) {
            float a = g1[tid] / sqrtf(v1[tid] + EPS);
            sa[tid] = a;
            sb[tid] = be1[tid] - m1[tid] * a;
        }
        __syncthreads();

        int idx = bid * 256 + tid;
        int b = idx / 196, p = idx % 196;
        int py = p / 14, px = p % 14;
        const float* xb = x + b * 784;

        u64 pr[4][3];
#pragma unroll
        for (int r = 0; r < 4; r++) {
            int rr = 2 * py - 1 + r; rr = min(max(rr, 0), 27);
            const float* xr = xb + rr * 28;
            int c0 = max(2 * px - 1, 0);
            int c3 = min(2 * px + 2, 27);
            float f0 = xr[c0];
            float f1 = xr[2 * px];
            float f2 = xr[2 * px + 1];
            float f3 = xr[c3];
            pr[r][0] = pack2(f0, f1);
            pr[r][1] = pack2(f1, f2);
            pr[r][2] = pack2(f2, f3);
        }

        u64 word = 0ULL;
        for (int co = 0; co < 64; co += 2) {
            u64 a00 = 0ULL, a01 = 0ULL, a10 = 0ULL, a11 = 0ULL;
            const u64* w0 = &sw[co * 9];
#pragma unroll
            for (int ky = 0; ky < 3; ky++)
#pragma unroll
                for (int kx = 0; kx < 3; kx++) {
                    u64 wa = w0[ky * 3 + kx], wb = w0[9 + ky * 3 + kx];
                    a00 = fma2(wa, pr[ky][kx], a00);
                    a01 = fma2(wa, pr[ky + 1][kx], a01);
                    a10 = fma2(wb, pr[ky][kx], a10);
                    a11 = fma2(wb, pr[ky + 1][kx], a11);
                }
            float v0, v1x, v2, v3;
            unpack2(a00, v0, v1x); unpack2(a01, v2, v3);
            float m0 = fmaxf(fmaxf(v0, v1x), fmaxf(v2, v3));
            unpack2(a10, v0, v1x); unpack2(a11, v2, v3);
            float m1v = fmaxf(fmaxf(v0, v1x), fmaxf(v2, v3));
            if (fmaf(sa[co], m0, sb[co]) >= 0.0f)          word |= 1ULL << co;
            if (fmaf(sa[co + 1], m1v, sb[co + 1]) >= 0.0f) word |= 1ULL << (co + 1);
        }
        g_bits1[b * 196 + p] = word;

    } else if (bid < NB_CONV1 + NB_FC1W) {
        // ---- fc1 weight pack role ----
        int o = bid - NB_CONV1;
        const float* wo = wfc1 + (long long)o * 3136;
#pragma unroll
        for (int it = 0; it < 13; it++) {
            int i = it * 256 + tid;
            bool v = (i < 3136) ? (wo[i] >= 0.0f) : false;
            u32 m = __ballot_sync(0xffffffffu, v);
            if ((tid & 31) == 0 && i < 3136) sbits[i >> 5] = m;
        }
        __syncthreads();
        if (tid < 98) {
            int j = tid % 49, half = tid / 49;
            u32 part = 0;
#pragma unroll
            for (int cc = 0; cc < 32; cc++) {
                int c = half * 32 + cc;
                int fi = c * 49 + j;
                part |= ((sbits[fi >> 5] >> (fi & 31)) & 1u) << cc;
            }
            sp[tid] = part;
        }
        __syncthreads();
        if (tid < 49)
            g_fc1bits[o * 49 + tid] = (u64)sp[tid] | ((u64)sp[tid + 49] << 32);

    } else {
        // ---- conv2 weight pack role ----
        int co = bid - NB_CONV1 - NB_FC1W;
        const float* wc = w2 + co * 576;
#pragma unroll
        for (int it = 0; it < 3; it++) {
            int i = it * 256 + tid;
            bool v = (i < 576) ? (wc[i] >= 0.0f) : false;
            u32 m = __ballot_sync(0xffffffffu, v);
            if ((tid & 31) == 0 && i < 576) sbits[i >> 5] = m;
        }
        __syncthreads();
        if (tid < 9) {
            u64 word = 0ULL;
#pragma unroll
            for (int cin = 0; cin < 64; cin++) {
                int fi = cin * 9 + tid;
                word |= (u64)((sbits[fi >> 5] >> (fi & 31)) & 1u) << cin;
            }
            g_w2bits[co * 9 + tid] = word;
        }
    }
}

// ================= tiny #2: bn folds =================
__global__ void k_bn(const float* __restrict__ g2, const float* __restrict__ be2,
                     const float* __restrict__ m2, const float* __restrict__ v2,
                     const float* __restrict__ g3, const float* __restrict__ be3,
                     const float* __restrict__ m3, const float* __restrict__ v3) {
    int i = blockIdx.x * 256 + threadIdx.x;
    if (i < 2048) {
        float a = g3[i] / sqrtf(v3[i] + EPS);
        g_a3[i] = a;
        g_b3[i] = be3[i] - m3[i] * a;
    }
    if (i < 64) {
        float a = g2[i] / sqrtf(v2[i] + EPS);
        g_a2[i] = a;
        g_b2[i] = be2[i] - m2[i] * a;
    }
}

// ================= tiny #3: fc2 weight pack =================
__global__ void k_fc2w(const float* __restrict__ wfc2) {
    __shared__ u32 sbits[64];
    int o = blockIdx.x;
    int tid = threadIdx.x;
    const float* wo = wfc2 + o * 2048;
#pragma unroll
    for (int it = 0; it < 8; it++) {
        int i = it * 256 + tid;
        u32 m = __ballot_sync(0xffffffffu, wo[i] >= 0.0f);
        if ((tid & 31) == 0) sbits[i >> 5] = m;
    }
    __syncthreads();
    if (tid < 32)
        g_fc2bits[o * 32 + tid] = (u64)sbits[2 * tid] | ((u64)sbits[2 * tid + 1] << 32);
}

// ================= conv2: window-split + CSA-9 (5 popcll instead of 9) =================
__global__ __launch_bounds__(256) void conv2_kernel() {
    __shared__ __align__(16) u64 sw[640];   // stride 10 per co
    __shared__ float sa[64], sb[64];
    int tid = threadIdx.x;
    for (int i = tid; i < 576; i += 256) {
        int co = i / 9, q = i - co * 9;
        sw[co * 10 + q] = g_w2bits[i];
    }
    if (tid < 64) { sa[tid] = g_a2[tid]; sb[tid] = g_b2[tid]; }
    __syncthreads();

    int gw = (blockIdx.x * 256 + tid) >> 5;
    int lane = tid & 31;
    int cg = gw & 3;
    int oct = gw >> 2;
    int o8 = lane >> 2;
    int spv = lane & 3;
    int pp = oct * 8 + o8;
    int b = pp / 49, p = pp % 49;
    int py = p / 7, px = p % 7;
    int dy = spv >> 1, dx = spv & 1;
    const u64* ib = g_bits1 + b * 196;

    u64 pix[9];
#pragma unroll
    for (int ky = 0; ky < 3; ky++) {
        int r = 2 * py - 1 + dy + ky; r = min(max(r, 0), 13);
#pragma unroll
        for (int kx = 0; kx < 3; kx++) {
            int c = 2 * px - 1 + dx + kx; c = min(max(c, 0), 13);
            pix[ky * 3 + kx] = ib[r * 14 + c];
        }
    }

    u32 bits16 = 0;
    int co0 = cg * 16;
#pragma unroll 4
    for (int t = 0; t < 16; t++) {
        const u64* wp = &sw[(co0 + t) * 10];
        // CSA tree: sum of 9 popcounts via 5 popcll
        u64 x0 = pix[0] ^ wp[0], x1 = pix[1] ^ wp[1], x2 = pix[2] ^ wp[2];
        u64 s1 = xor3(x0, x1, x2), c1 = maj3(x0, x1, x2);
        x0 = pix[3] ^ wp[3]; x1 = pix[4] ^ wp[4]; x2 = pix[5] ^ wp[5];
        u64 s2 = xor3(x0, x1, x2), c2 = maj3(x0, x1, x2);
        x0 = pix[6] ^ wp[6]; x1 = pix[7] ^ wp[7]; x2 = pix[8] ^ wp[8];
        u64 s3 = xor3(x0, x1, x2), c3 = maj3(x0, x1, x2);
        u64 ss = xor3(s1, s2, s3), sc = maj3(s1, s2, s3);
        int s = (int)__popcll(ss) +
                2 * (int)(__popcll(sc) + __popcll(c1) + __popcll(c2) + __popcll(c3));
        s = min(s, __shfl_xor_sync(0xffffffffu, s, 1));
        s = min(s, __shfl_xor_sync(0xffffffffu, s, 2));
        float d = (float)(576 - 2 * s);
        if (fmaf(sa[co0 + t], d, sb[co0 + t]) >= 0.0f) bits16 |= 1u << t;
    }
    if (spv == 0)
        ((u16*)g_bits2)[pp * 4 + cg] = (u16)bits16;
}

// ================= fc1: 64x64 XNOR GEMM with CSA-3 over k (2 popcll per 3 words) =======
__device__ __forceinline__ void fc1_csa_groups(const u64 (&sA)[64][25], const u64 (&sB)[64][25],
                                               int tx, int ty, int (&acc)[4][4], int ngroups) {
#pragma unroll 2
    for (int g = 0; g < ngroups; g++) {
        int kk = g * 3;
        u64 A0[4], A1[4], A2[4];
#pragma unroll
        for (int i = 0; i < 4; i++) {
            A0[i] = sA[ty + 16 * i][kk];
            A1[i] = sA[ty + 16 * i][kk + 1];
            A2[i] = sA[ty + 16 * i][kk + 2];
        }
#pragma unroll
        for (int j = 0; j < 4; j++) {
            const u64* br = &sB[tx + 16 * j][kk];
            u64 b0 = br[0], b1 = br[1], b2 = br[2];
#pragma unroll
            for (int i = 0; i < 4; i++) {
                u64 x0 = A0[i] ^ b0, x1 = A1[i] ^ b1, x2 = A2[i] ^ b2;
                u64 s = xor3(x0, x1, x2);
                u64 c = maj3(x0, x1, x2);
                acc[i][j] += (int)__popcll(s) + 2 * (int)__popcll(c);
            }
        }
    }
}

__global__ __launch_bounds__(256) void fc1_kernel() {
    __shared__ u64 sA[64][25];
    __shared__ u64 sB[64][25];
    __shared__ u64 obits[64];
    __shared__ float sa3[64], sb3[64];
    int tid = threadIdx.x;
    int tx = tid & 15, ty = tid >> 4;
    int m0 = blockIdx.y * 64;
    int n0 = blockIdx.x * 64;

    if (tid < 64) {
        obits[tid] = 0ULL;
        sa3[tid] = g_a3[n0 + tid];
        sb3[tid] = g_b3[n0 + tid];
    }

    int acc[4][4];
#pragma unroll
    for (int i = 0; i < 4; i++)
#pragma unroll
        for (int j = 0; j < 4; j++) acc[i][j] = 0;

    // phase 0: k words [0,25): 8 CSA-3 groups + single column 24
    for (int e = tid; e < 64 * 25; e += 256) {
        int r = e / 25, kk = e % 25;
        sA[r][kk] = g_bits2[(m0 + r) * 49 + kk];
        sB[r][kk] = g_fc1bits[(n0 + r) * 49 + kk];
    }
    __syncthreads();
    fc1_csa_groups(sA, sB, tx, ty, acc, 8);
    {   // single remainder column kk=24
        u64 a0 = sA[ty][24], a1 = sA[ty + 16][24], a2 = sA[ty + 32][24], a3 = sA[ty + 48][24];
        u64 b0 = sB[tx][24], b1 = sB[tx + 16][24], b2 = sB[tx + 32][24], b3 = sB[tx + 48][24];
        acc[0][0] += __popcll(a0 ^ b0); acc[0][1] += __popcll(a0 ^ b1);
        acc[0][2] += __popcll(a0 ^ b2); acc[0][3] += __popcll(a0 ^ b3);
        acc[1][0] += __popcll(a1 ^ b0); acc[1][1] += __popcll(a1 ^ b1);
        acc[1][2] += __popcll(a1 ^ b2); acc[1][3] += __popcll(a1 ^ b3);
        acc[2][0] += __popcll(a2 ^ b0); acc[2][1] += __popcll(a2 ^ b1);
        acc[2][2] += __popcll(a2 ^ b2); acc[2][3] += __popcll(a2 ^ b3);
        acc[3][0] += __popcll(a3 ^ b0); acc[3][1] += __popcll(a3 ^ b1);
        acc[3][2] += __popcll(a3 ^ b2); acc[3][3] += __popcll(a3 ^ b3);
    }
    __syncthreads();
    // phase 1: k words [25,49): 24 words = 8 CSA-3 groups
    for (int e = tid; e < 64 * 24; e += 256) {
        int r = e / 24, kk = e % 24;
        sA[r][kk] = g_bits2[(m0 + r) * 49 + 25 + kk];
        sB[r][kk] = g_fc1bits[(n0 + r) * 49 + 25 + kk];
    }
    __syncthreads();
    fc1_csa_groups(sA, sB, tx, ty, acc, 8);

#pragma unroll
    for (int i = 0; i < 4; i++) {
        u64 bits = 0ULL;
#pragma unroll
        for (int j = 0; j < 4; j++) {
            int c = tx + 16 * j;
            float d = (float)(3136 - 2 * acc[i][j]);
            if (fmaf(sa3[c], d, sb3[c]) >= 0.0f) bits |= 1ULL << c;
        }
        atomicOr(&obits[ty + 16 * i], bits);
    }
    __syncthreads();
    if (tid < 64)
        g_bits3[(m0 + tid) * 32 + blockIdx.x] = obits[tid];
}

// ================= fc2: warp-per-row XNOR + scale (known-good) =================
__global__ __launch_bounds__(256) void fc2_kernel(float* __restrict__ out,
                                                  const float* __restrict__ scale) {
    __shared__ u64 sw[10][32];
    int tid = threadIdx.x;
    for (int i = tid; i < 320; i += 256)
        ((u64*)sw)[i] = g_fc2bits[i];
    __syncthreads();

    int warp = tid >> 5, lane = tid & 31;
    int b = blockIdx.x * 8 + warp;
    u64 xw = g_bits3[b * 32 + lane];
    float sc = scale[0];
#pragma unroll
    for (int o = 0; o < 10; o++) {
        u32 p = (u32)__popcll(xw ^ sw[o][lane]);
        u32 s = __reduce_add_sync(0xffffffffu, p);
        if (lane == o)
            out[b * 10 + o] = sc * (float)(2048 - 2 * (int)s);
    }
}

// ================= launch =================
extern "C" void kernel_launch(void* const* d_in, const int* in_sizes, int n_in,
                              void* d_out, int out_size) {
    const float* x       = (const float*)d_in[0];
    const float* conv1_w = (const float*)d_in[1];
    const float* bn1_g   = (const float*)d_in[2];
    const float* bn1_b   = (const float*)d_in[3];
    const float* bn1_m   = (const float*)d_in[4];
    const float* bn1_v   = (const float*)d_in[5];
    const float* conv2_w = (const float*)d_in[6];
    const float* bn2_g   = (const float*)d_in[7];
    const float* bn2_b   = (const float*)d_in[8];
    const float* bn2_m   = (const float*)d_in[9];
    const float* bn2_v   = (const float*)d_in[10];
    const float* fc1_w   = (const float*)d_in[11];
    const float* bn3_g   = (const float*)d_in[12];
    const float* bn3_b   = (const float*)d_in[13];
    const float* bn3_m   = (const float*)d_in[14];
    const float* bn3_v   = (const float*)d_in[15];
    const float* fc2_w   = (const float*)d_in[16];
    const float* scale   = (const float*)d_in[17];
    float* out = (float*)d_out;

    // launch order: conv2 is #4 (profiler slot)
    kA<<<NB_KA, 256>>>(x, conv1_w, bn1_g, bn1_b, bn1_m, bn1_v, conv2_w, fc1_w);
    k_bn<<<8, 256>>>(bn2_g, bn2_b, bn2_m, bn2_v, bn3_g, bn3_b, bn3_m, bn3_v);
    k_fc2w<<<10, 256>>>(fc2_w);
    conv2_kernel<<<6272, 256>>>();
    fc1_kernel<<<dim3(32, 32), 256>>>();
    fc2_kernel<<<256, 256>>>(out, scale);
}

// round 17
// speedup vs baseline: 1.1730x; 1.0179x over previous
#include <cuda_runtime.h>
#include <cuda_bf16.h>
#include <cstdint>

#define EPS 1e-5f
typedef unsigned long long u64;
typedef unsigned int u32;
typedef unsigned short u16;

// ---------------- device scratch ----------------
__device__ float g_a2[64], g_b2[64];
__device__ float g_a3[2048], g_b3[2048];
__device__ u64 g_w2bits[64 * 9];
__device__ u64 g_fc1bits[2048 * 49];
__device__ u64 g_fc2bits[10 * 32];
__device__ u64 g_bits1[2048 * 14 * 14];
__device__ u64 g_bits2[2048 * 7 * 7];
__device__ u64 g_bits3[2048 * 32];

// ---------------- helpers ----------------
__device__ __forceinline__ u64 fma2(u64 a, u64 b, u64 c) {
    u64 d;
    asm("fma.rn.f32x2 %0, %1, %2, %3;" : "=l"(d) : "l"(a), "l"(b), "l"(c));
    return d;
}
__device__ __forceinline__ u64 pack2(float lo, float hi) {
    u64 d;
    asm("mov.b64 %0, {%1, %2};" : "=l"(d) : "f"(lo), "f"(hi));
    return d;
}
__device__ __forceinline__ void unpack2(u64 v, float& lo, float& hi) {
    asm("mov.b64 {%0, %1}, %2;" : "=f"(lo), "=f"(hi) : "l"(v));
}
__device__ __forceinline__ u64 xor3(u64 a, u64 b, u64 c) { return a ^ b ^ c; }
__device__ __forceinline__ u64 maj3(u64 a, u64 b, u64 c) { return (a & b) | (c & (a ^ b)); }

// ================= role: conv1 half-batch (known-good math) =================
__device__ __forceinline__ void role_conv1(
    u64* sw, float* sa, float* sb,
    const float* __restrict__ x, const float* __restrict__ w1,
    const float* __restrict__ g1, const float* __restrict__ be1,
    const float* __restrict__ m1, const float* __restrict__ v1,
    int lbid, int batch0)
{
    int tid = threadIdx.x;
    for (int i = tid; i < 576; i += 256) {
        float s = (w1[i] >= 0.0f) ? 1.0f : -1.0f;
        sw[i] = pack2(s, s);
    }
    if (tid < 64) {
        float a = g1[tid] / sqrtf(v1[tid] + EPS);
        sa[tid] = a;
        sb[tid] = be1[tid] - m1[tid] * a;
    }
    __syncthreads();

    int idx = lbid * 256 + tid;            // [0, 1024*196)
    int b = batch0 + idx / 196, p = idx % 196;
    int py = p / 14, px = p % 14;
    const float* xb = x + b * 784;

    u64 pr[4][3];
#pragma unroll
    for (int r = 0; r < 4; r++) {
        int rr = 2 * py - 1 + r; rr = min(max(rr, 0), 27);
        const float* xr = xb + rr * 28;
        int c0 = max(2 * px - 1, 0);
        int c3 = min(2 * px + 2, 27);
        float f0 = xr[c0];
        float f1 = xr[2 * px];
        float f2 = xr[2 * px + 1];
        float f3 = xr[c3];
        pr[r][0] = pack2(f0, f1);
        pr[r][1] = pack2(f1, f2);
        pr[r][2] = pack2(f2, f3);
    }

    u64 word = 0ULL;
    for (int co = 0; co < 64; co += 2) {
        u64 a00 = 0ULL, a01 = 0ULL, a10 = 0ULL, a11 = 0ULL;
        const u64* w0 = &sw[co * 9];
#pragma unroll
        for (int ky = 0; ky < 3; ky++)
#pragma unroll
            for (int kx = 0; kx < 3; kx++) {
                u64 wa = w0[ky * 3 + kx], wb = w0[9 + ky * 3 + kx];
                a00 = fma2(wa, pr[ky][kx], a00);
                a01 = fma2(wa, pr[ky + 1][kx], a01);
                a10 = fma2(wb, pr[ky][kx], a10);
                a11 = fma2(wb, pr[ky + 1][kx], a11);
            }
        float v0, v1x, v2, v3;
        unpack2(a00, v0, v1x); unpack2(a01, v2, v3);
        float m0 = fmaxf(fmaxf(v0, v1x), fmaxf(v2, v3));
        unpack2(a10, v0, v1x); unpack2(a11, v2, v3);
        float m1v = fmaxf(fmaxf(v0, v1x), fmaxf(v2, v3));
        if (fmaf(sa[co], m0, sb[co]) >= 0.0f)          word |= 1ULL << co;
        if (fmaf(sa[co + 1], m1v, sb[co + 1]) >= 0.0f) word |= 1ULL << (co + 1);
    }
    g_bits1[b * 196 + p] = word;
}

// ================= role: conv2 half-batch, window-split + CSA-9 (r16 math) =================
__device__ __forceinline__ void role_conv2(u64* sw /*640*/, float* sa, float* sb,
                                           int lbid, int pix_base)
{
    int tid = threadIdx.x;
    for (int i = tid; i < 576; i += 256) {
        int co = i / 9, q = i - co * 9;
        sw[co * 10 + q] = g_w2bits[i];
    }
    if (tid < 64) { sa[tid] = g_a2[tid]; sb[tid] = g_b2[tid]; }
    __syncthreads();

    int gw = (lbid * 256 + tid) >> 5;        // local warp [0, 25088)
    int lane = tid & 31;
    int cg = gw & 3;                          // uniform within warp
    int oct = gw >> 2;                        // [0, 6272)
    int o8 = lane >> 2;
    int spv = lane & 3;
    int pp = pix_base + oct * 8 + o8;         // pooled pixel
    int b = pp / 49, p = pp % 49;
    int py = p / 7, px = p % 7;
    int dy = spv >> 1, dx = spv & 1;
    const u64* ib = g_bits1 + b * 196;

    u64 pix[9];
#pragma unroll
    for (int ky = 0; ky < 3; ky++) {
        int r = 2 * py - 1 + dy + ky; r = min(max(r, 0), 13);
#pragma unroll
        for (int kx = 0; kx < 3; kx++) {
            int c = 2 * px - 1 + dx + kx; c = min(max(c, 0), 13);
            pix[ky * 3 + kx] = ib[r * 14 + c];
        }
    }

    u32 bits16 = 0;
    int co0 = cg * 16;
#pragma unroll 4
    for (int t = 0; t < 16; t++) {
        const u64* wp = &sw[(co0 + t) * 10];
        u64 x0 = pix[0] ^ wp[0], x1 = pix[1] ^ wp[1], x2 = pix[2] ^ wp[2];
        u64 s1 = xor3(x0, x1, x2), c1 = maj3(x0, x1, x2);
        x0 = pix[3] ^ wp[3]; x1 = pix[4] ^ wp[4]; x2 = pix[5] ^ wp[5];
        u64 s2 = xor3(x0, x1, x2), c2 = maj3(x0, x1, x2);
        x0 = pix[6] ^ wp[6]; x1 = pix[7] ^ wp[7]; x2 = pix[8] ^ wp[8];
        u64 s3 = xor3(x0, x1, x2), c3 = maj3(x0, x1, x2);
        u64 ss = xor3(s1, s2, s3), sc = maj3(s1, s2, s3);
        int s = (int)__popcll(ss) +
                2 * (int)(__popcll(sc) + __popcll(c1) + __popcll(c2) + __popcll(c3));
        s = min(s, __shfl_xor_sync(0xffffffffu, s, 1));
        s = min(s, __shfl_xor_sync(0xffffffffu, s, 2));
        float d = (float)(576 - 2 * s);
        if (fmaf(sa[co0 + t], d, sb[co0 + t]) >= 0.0f) bits16 |= 1u << t;
    }
    if (spv == 0)
        ((u16*)g_bits2)[pp * 4 + cg] = (u16)bits16;
}

// ================= kA: conv1(h1) + ALL weight packs =================
#define NB_C1H   784
#define NB_FC1W  2048
#define NB_W2    64
#define NB_FC2W  10
#define NB_BN    8
#define NB_KA (NB_C1H + NB_FC1W + NB_W2 + NB_FC2W + NB_BN)

__global__ __launch_bounds__(256, 4) void kA(
    const float* __restrict__ x, const float* __restrict__ w1,
    const float* __restrict__ g1, const float* __restrict__ be1,
    const float* __restrict__ m1, const float* __restrict__ v1,
    const float* __restrict__ w2,
    const float* __restrict__ wfc1,
    const float* __restrict__ g2, const float* __restrict__ be2,
    const float* __restrict__ m2, const float* __restrict__ v2,
    const float* __restrict__ g3, const float* __restrict__ be3,
    const float* __restrict__ m3, const float* __restrict__ v3,
    const float* __restrict__ wfc2)
{
    __shared__ __align__(16) u64 sw[576];
    __shared__ float sa[64], sb[64];
    __shared__ u32 sbits[98];
    __shared__ u32 sp[98];

    int bid = blockIdx.x;
    int tid = threadIdx.x;

    if (bid < NB_C1H) {
        role_conv1(sw, sa, sb, x, w1, g1, be1, m1, v1, bid, 0);

    } else if (bid < NB_C1H + NB_FC1W) {
        // ---- fc1 weight pack ----
        int o = bid - NB_C1H;
        const float* wo = wfc1 + (long long)o * 3136;
#pragma unroll
        for (int it = 0; it < 13; it++) {
            int i = it * 256 + tid;
            bool v = (i < 3136) ? (wo[i] >= 0.0f) : false;
            u32 m = __ballot_sync(0xffffffffu, v);
            if ((tid & 31) == 0 && i < 3136) sbits[i >> 5] = m;
        }
        __syncthreads();
        if (tid < 98) {
            int j = tid % 49, half = tid / 49;
            u32 part = 0;
#pragma unroll
            for (int cc = 0; cc < 32; cc++) {
                int c = half * 32 + cc;
                int fi = c * 49 + j;
                part |= ((sbits[fi >> 5] >> (fi & 31)) & 1u) << cc;
            }
            sp[tid] = part;
        }
        __syncthreads();
        if (tid < 49)
            g_fc1bits[o * 49 + tid] = (u64)sp[tid] | ((u64)sp[tid + 49] << 32);

    } else if (bid < NB_C1H + NB_FC1W + NB_W2) {
        // ---- conv2 weight pack ----
        int co = bid - NB_C1H - NB_FC1W;
        const float* wc = w2 + co * 576;
#pragma unroll
        for (int it = 0; it < 3; it++) {
            int i = it * 256 + tid;
            bool v = (i < 576) ? (wc[i] >= 0.0f) : false;
            u32 m = __ballot_sync(0xffffffffu, v);
            if ((tid & 31) == 0 && i < 576) sbits[i >> 5] = m;
        }
        __syncthreads();
        if (tid < 9) {
            u64 word = 0ULL;
#pragma unroll
            for (int cin = 0; cin < 64; cin++) {
                int fi = cin * 9 + tid;
                word |= (u64)((sbits[fi >> 5] >> (fi & 31)) & 1u) << cin;
            }
            g_w2bits[co * 9 + tid] = word;
        }

    } else if (bid < NB_C1H + NB_FC1W + NB_W2 + NB_FC2W) {
        // ---- fc2 weight pack ----
        int o = bid - NB_C1H - NB_FC1W - NB_W2;
        const float* wo = wfc2 + o * 2048;
#pragma unroll
        for (int it = 0; it < 8; it++) {
            int i = it * 256 + tid;
            u32 m = __ballot_sync(0xffffffffu, wo[i] >= 0.0f);
            if ((tid & 31) == 0) sbits[i >> 5] = m;
        }
        __syncthreads();
        if (tid < 32)
            g_fc2bits[o * 32 + tid] = (u64)sbits[2 * tid] | ((u64)sbits[2 * tid + 1] << 32);

    } else {
        // ---- bn folds ----
        int i = (bid - NB_C1H - NB_FC1W - NB_W2 - NB_FC2W) * 256 + tid;
        if (i < 2048) {
            float a = g3[i] / sqrtf(v3[i] + EPS);
            g_a3[i] = a;
            g_b3[i] = be3[i] - m3[i] * a;
        }
        if (i < 64) {
            float a = g2[i] / sqrtf(v2[i] + EPS);
            g_a2[i] = a;
            g_b2[i] = be2[i] - m2[i] * a;
        }
    }
}

// ================= kB: conv2(h1) || conv1(h2) — fma/alu pipe overlap =================
#define NB_C2H 3136
__global__ __launch_bounds__(256, 4) void kB(
    const float* __restrict__ x, const float* __restrict__ w1,
    const float* __restrict__ g1, const float* __restrict__ be1,
    const float* __restrict__ m1, const float* __restrict__ v1)
{
    __shared__ __align__(16) u64 sw[640];
    __shared__ float sa[64], sb[64];
    int bid = blockIdx.x;
    if (bid < NB_C2H) role_conv2(sw, sa, sb, bid, 0);
    else              role_conv1(sw, sa, sb, x, w1, g1, be1, m1, v1, bid - NB_C2H, 1024);
}

// ================= kC: conv2(h2) =================
__global__ __launch_bounds__(256) void kC() {
    __shared__ __align__(16) u64 sw[640];
    __shared__ float sa[64], sb[64];
    role_conv2(sw, sa, sb, blockIdx.x, 1024 * 49);
}

// ================= fc1: 64x64 XNOR GEMM + CSA-3 (r16 known-good) =================
__device__ __forceinline__ void fc1_csa_groups(const u64 (&sA)[64][25], const u64 (&sB)[64][25],
                                               int tx, int ty, int (&acc)[4][4], int ngroups) {
#pragma unroll 2
    for (int g = 0; g < ngroups; g++) {
        int kk = g * 3;
        u64 A0[4], A1[4], A2[4];
#pragma unroll
        for (int i = 0; i < 4; i++) {
            A0[i] = sA[ty + 16 * i][kk];
            A1[i] = sA[ty + 16 * i][kk + 1];
            A2[i] = sA[ty + 16 * i][kk + 2];
        }
#pragma unroll
        for (int j = 0; j < 4; j++) {
            const u64* br = &sB[tx + 16 * j][kk];
            u64 b0 = br[0], b1 = br[1], b2 = br[2];
#pragma unroll
            for (int i = 0; i < 4; i++) {
                u64 x0 = A0[i] ^ b0, x1 = A1[i] ^ b1, x2 = A2[i] ^ b2;
                u64 s = xor3(x0, x1, x2);
                u64 c = maj3(x0, x1, x2);
                acc[i][j] += (int)__popcll(s) + 2 * (int)__popcll(c);
            }
        }
    }
}

__global__ __launch_bounds__(256) void fc1_kernel() {
    __shared__ u64 sA[64][25];
    __shared__ u64 sB[64][25];
    __shared__ u64 obits[64];
    __shared__ float sa3[64], sb3[64];
    int tid = threadIdx.x;
    int tx = tid & 15, ty = tid >> 4;
    int m0 = blockIdx.y * 64;
    int n0 = blockIdx.x * 64;

    if (tid < 64) {
        obits[tid] = 0ULL;
        sa3[tid] = g_a3[n0 + tid];
        sb3[tid] = g_b3[n0 + tid];
    }

    int acc[4][4];
#pragma unroll
    for (int i = 0; i < 4; i++)
#pragma unroll
        for (int j = 0; j < 4; j++) acc[i][j] = 0;

    for (int e = tid; e < 64 * 25; e += 256) {
        int r = e / 25, kk = e % 25;
        sA[r][kk] = g_bits2[(m0 + r) * 49 + kk];
        sB[r][kk] = g_fc1bits[(n0 + r) * 49 + kk];
    }
    __syncthreads();
    fc1_csa_groups(sA, sB, tx, ty, acc, 8);
    {
        u64 a0 = sA[ty][24], a1 = sA[ty + 16][24], a2 = sA[ty + 32][24], a3 = sA[ty + 48][24];
        u64 b0 = sB[tx][24], b1 = sB[tx + 16][24], b2 = sB[tx + 32][24], b3 = sB[tx + 48][24];
        acc[0][0] += __popcll(a0 ^ b0); acc[0][1] += __popcll(a0 ^ b1);
        acc[0][2] += __popcll(a0 ^ b2); acc[0][3] += __popcll(a0 ^ b3);
        acc[1][0] += __popcll(a1 ^ b0); acc[1][1] += __popcll(a1 ^ b1);
        acc[1][2] += __popcll(a1 ^ b2); acc[1][3] += __popcll(a1 ^ b3);
        acc[2][0] += __popcll(a2 ^ b0); acc[2][1] += __popcll(a2 ^ b1);
        acc[2][2] += __popcll(a2 ^ b2); acc[2][3] += __popcll(a2 ^ b3);
        acc[3][0] += __popcll(a3 ^ b0); acc[3][1] += __popcll(a3 ^ b1);
        acc[3][2] += __popcll(a3 ^ b2); acc[3][3] += __popcll(a3 ^ b3);
    }
    __syncthreads();
    for (int e = tid; e < 64 * 24; e += 256) {
        int r = e / 24, kk = e % 24;
        sA[r][kk] = g_bits2[(m0 + r) * 49 + 25 + kk];
        sB[r][kk] = g_fc1bits[(n0 + r) * 49 + 25 + kk];
    }
    __syncthreads();
    fc1_csa_groups(sA, sB, tx, ty, acc, 8);

#pragma unroll
    for (int i = 0; i < 4; i++) {
        u64 bits = 0ULL;
#pragma unroll
        for (int j = 0; j < 4; j++) {
            int c = tx + 16 * j;
            float d = (float)(3136 - 2 * acc[i][j]);
            if (fmaf(sa3[c], d, sb3[c]) >= 0.0f) bits |= 1ULL << c;
        }
        atomicOr(&obits[ty + 16 * i], bits);
    }
    __syncthreads();
    if (tid < 64)
        g_bits3[(m0 + tid) * 32 + blockIdx.x] = obits[tid];
}

// ================= fc2: warp-per-row XNOR + scale (known-good) =================
__global__ __launch_bounds__(256) void fc2_kernel(float* __restrict__ out,
                                                  const float* __restrict__ scale) {
    __shared__ u64 sw[10][32];
    int tid = threadIdx.x;
    for (int i = tid; i < 320; i += 256)
        ((u64*)sw)[i] = g_fc2bits[i];
    __syncthreads();

    int warp = tid >> 5, lane = tid & 31;
    int b = blockIdx.x * 8 + warp;
    u64 xw = g_bits3[b * 32 + lane];
    float sc = scale[0];
#pragma unroll
    for (int o = 0; o < 10; o++) {
        u32 p = (u32)__popcll(xw ^ sw[o][lane]);
        u32 s = __reduce_add_sync(0xffffffffu, p);
        if (lane == o)
            out[b * 10 + o] = sc * (float)(2048 - 2 * (int)s);
    }
}

// ================= launch =================
extern "C" void kernel_launch(void* const* d_in, const int* in_sizes, int n_in,
                              void* d_out, int out_size) {
    const float* x       = (const float*)d_in[0];
    const float* conv1_w = (const float*)d_in[1];
    const float* bn1_g   = (const float*)d_in[2];
    const float* bn1_b   = (const float*)d_in[3];
    const float* bn1_m   = (const float*)d_in[4];
    const float* bn1_v   = (const float*)d_in[5];
    const float* conv2_w = (const float*)d_in[6];
    const float* bn2_g   = (const float*)d_in[7];
    const float* bn2_b   = (const float*)d_in[8];
    const float* bn2_m   = (const float*)d_in[9];
    const float* bn2_v   = (const float*)d_in[10];
    const float* fc1_w   = (const float*)d_in[11];
    const float* bn3_g   = (const float*)d_in[12];
    const float* bn3_b   = (const float*)d_in[13];
    const float* bn3_m   = (const float*)d_in[14];
    const float* bn3_v   = (const float*)d_in[15];
    const float* fc2_w   = (const float*)d_in[16];
    const float* scale   = (const float*)d_in[17];
    float* out = (float*)d_out;

    // launch order: fc1 is #4 (profiler slot -> get fc1-CSA profile)
    kA<<<NB_KA, 256>>>(x, conv1_w, bn1_g, bn1_b, bn1_m, bn1_v,
                       conv2_w, fc1_w,
                       bn2_g, bn2_b, bn2_m, bn2_v,
                       bn3_g, bn3_b, bn3_m, bn3_v, fc2_w);
    kB<<<NB_C2H + NB_C1H, 256>>>(x, conv1_w, bn1_g, bn1_b, bn1_m, bn1_v);
    kC<<<NB_C2H, 256>>>();
    fc1_kernel<<<dim3(32, 32), 256>>>();
    fc2_kernel<<<256, 256>>>(out, scale);
}